// round 13
// baseline (speedup 1.0000x reference)
#include <cuda_runtime.h>
#include <type_traits>
#include <cstddef>

namespace so3 {

constexpr int LMAX  = 8;
constexpr int NCOEF = (LMAX + 1) * (LMAX + 1);   // 81 per batch per array
constexpr int NCMP  = 45;                        // compact m>=0 coefficients
constexpr int TPB   = 128;
constexpr int EPB   = 32;                        // batch elements per block (one per lane)
constexpr int NGRP  = 4;                         // pair groups = warps per block

// ---------------- compile-time math ----------------
__host__ __device__ constexpr double fact(int n) { double r = 1.0; for (int i = 2; i <= n; ++i) r *= (double)i; return r; }
__host__ __device__ constexpr double csqrt(double x) {
    if (x <= 0.0) return 0.0;
    double g = x > 1.0 ? x : 1.0;
    for (int i = 0; i < 64; ++i) g = 0.5 * (g + x / g);
    return g;
}
__host__ __device__ constexpr int iabs(int x) { return x < 0 ? -x : x; }
__host__ __device__ constexpr int imin(int a, int b) { return a < b ? a : b; }
__host__ __device__ constexpr int imax(int a, int b) { return a > b ? a : b; }
__host__ __device__ constexpr int cpos(int l, int m) { return l * (l + 1) / 2 + m; }   // 0..44

// Clebsch-Gordan <j1 m1 j2 m2 | j3 m3>, Racah formula (matches reference)
__host__ __device__ constexpr double cg(int j1, int m1, int j2, int m2, int j3, int m3) {
    if (m1 + m2 != m3) return 0.0;
    if (j3 < iabs(j1 - j2) || j3 > j1 + j2) return 0.0;
    if (iabs(m1) > j1 || iabs(m2) > j2 || iabs(m3) > j3) return 0.0;
    double pre = csqrt((2.0 * j3 + 1.0) * fact(j1 + j2 - j3) * fact(j1 - j2 + j3) *
                       fact(-j1 + j2 + j3) / fact(j1 + j2 + j3 + 1));
    pre *= csqrt(fact(j1 + m1) * fact(j1 - m1) * fact(j2 + m2) * fact(j2 - m2) *
                 fact(j3 + m3) * fact(j3 - m3));
    int kmin = imax(0, imax(j2 - j3 - m1, j1 - j3 + m2));
    int kmax = imin(j1 + j2 - j3, imin(j1 - m1, j2 + m2));
    double s = 0.0;
    for (int k = kmin; k <= kmax; ++k) {
        double d = fact(k) * fact(j1 + j2 - j3 - k) * fact(j1 - m1 - k) *
                   fact(j2 + m2 - k) * fact(j3 - j2 + m1 + k) * fact(j3 - j1 - m2 + k);
        s += ((k & 1) ? -1.0 : 1.0) / d;
    }
    return pre * s;
}

// ---------------- output index maps (mirror reference builders) ----------------
__host__ __device__ constexpr int full_index(int a, int b, int c) {
    int idx = 0;
    for (int l1 = 0; l1 <= LMAX; ++l1)
        for (int l2 = l1; l2 <= LMAX; ++l2)
            for (int lv = l2 - l1; lv <= imin(l1 + l2, LMAX); ++lv) {
                if (l1 == a && l2 == b && lv == c) return idx;
                ++idx;
            }
    return -1;
}
__host__ __device__ constexpr int count_full() {
    int idx = 0;
    for (int l1 = 0; l1 <= LMAX; ++l1)
        for (int l2 = l1; l2 <= LMAX; ++l2)
            for (int lv = l2 - l1; lv <= imin(l1 + l2, LMAX); ++lv) ++idx;
    return idx;
}
constexpr int NFULL = count_full();
static_assert(NFULL == 215, "FULL map size mismatch");

__host__ __device__ constexpr int power_index_impl(int a, int b, int c) {
    int idx = 0;
    for (int l2 = 2; l2 <= LMAX; ++l2) {
        if (a == 1 && b == l2 && c == l2 - 1) return idx;
        ++idx;
        if (l2 >= 4 && (l2 - 1) + 1 <= imin(l2 + 1, LMAX)) {
            if (a == 1 && b == l2 && c == l2) return idx;
            ++idx;
        }
    }
    for (int l2 = 3; l2 <= LMAX; ++l2) {
        if (a == 2 && b == l2 && c == l2 - 2) return idx;
        ++idx;
        if ((l2 - 2) + 1 <= imin(l2 + 2, LMAX)) {
            if (a == 2 && b == l2 && c == l2 - 1) return idx;
            ++idx;
        }
    }
    if (LMAX >= 3) {
        if (a == 3 && b == 3 && c == 2) return idx;
        ++idx;
    }
    for (int l2 = 4; l2 <= LMAX; ++l2) {
        if (a == 3 && b == l2 && c == l2 - 3) return idx;
        ++idx;
        if ((l2 % 2 == 1) && l2 >= 5) {
            if ((l2 - 3) + 1 <= imin(l2 + 3, LMAX)) {
                if (a == 3 && b == l2 && c == l2 - 2) return idx;
                ++idx;
            }
            if ((l2 - 3) + 2 <= imin(l2 + 3, LMAX)) {
                if (a == 3 && b == l2 && c == l2 - 1) return idx;
                ++idx;
            }
        }
    }
    return 1000 + idx;
}
__host__ __device__ constexpr int power_index(int a, int b, int c) {
    return power_index_impl(a, b, c) >= 1000 ? -1 : power_index_impl(a, b, c);
}
constexpr int NPOWER = power_index_impl(-9, -9, -9) - 1000;
static_assert(NPOWER == 34, "POWER map size mismatch");
constexpr int NOUT = NFULL + NPOWER;   // 249

// ---------------- compile-time pair partition (greedy, largest-first) ----------------
constexpr int NPAIRS = (LMAX + 1) * (LMAX + 2) / 2;   // 45

__host__ __device__ constexpr int pair_index(int a, int b) {
    int idx = 0;
    for (int l1 = 0; l1 <= LMAX; ++l1)
        for (int l2 = l1; l2 <= LMAX; ++l2) { if (l1 == a && l2 == b) return idx; ++idx; }
    return -1;
}

// Analytic FFMA-issue cost proxy of one (l1,l2) pair — NO cg() calls (cheap constexpr).
// CG tensors over the (m1,m2) grid are ~dense in the allowed region, so
// (#m1 terms) * (#lo values) tracks true FMA count closely enough for balancing.
__host__ __device__ constexpr long pair_cost(int l1, int l2) {
    long c = 0;
    const int lomin = l2 - l1, lomax = imin(l1 + l2, LMAX);
    for (int M = -(l1 + l2); M <= l1 + l2; ++M) {
        int lstart = imax(lomin, iabs(M));
        if (lstart > lomax) continue;
        int nlo = lomax - lstart + 1;
        for (int m1 = imax(-l1, M - l2); m1 <= imin(l1, M + l2); ++m1) {
            int m2 = M - m1;
            if (l1 == l2 && m1 > m2) continue;
            c += 6 + 2L * nlo;          // complex product + CG FMAs
        }
        for (int lo = lstart; lo <= lomax; ++lo) {
            c += 6;                     // beta dot + f3 fetch
            if (power_index(l1, l2, lo) >= 0) c += 4;
        }
    }
    return c;
}

struct PairAssign { int grp[NPAIRS]; };

__host__ __device__ constexpr PairAssign assign_pairs() {
    long cost[NPAIRS] = {};
    {
        int idx = 0;
        for (int l1 = 0; l1 <= LMAX; ++l1)
            for (int l2 = l1; l2 <= LMAX; ++l2) { cost[idx] = pair_cost(l1, l2); ++idx; }
    }
    bool used[NPAIRS] = {};
    long load[NGRP] = {};
    PairAssign pa = {};
    for (int it = 0; it < NPAIRS; ++it) {
        int best = -1;
        for (int p = 0; p < NPAIRS; ++p)
            if (!used[p] && (best < 0 || cost[p] > cost[best])) best = p;
        int g = 0;
        for (int k = 1; k < NGRP; ++k) if (load[k] < load[g]) g = k;
        pa.grp[best] = g; load[g] += cost[best]; used[best] = true;
    }
    return pa;
}
constexpr PairAssign PA = assign_pairs();
__host__ __device__ constexpr int pair_group(int l1, int l2) { return PA.grp[pair_index(l1, l2)]; }

// ---------------- static-for ----------------
template <int I, int N, class F>
__device__ __forceinline__ void sfor(F&& f) {
    if constexpr (I < N) {
        f(std::integral_constant<int, I>{});
        sfor<I + 1, N>(f);
    }
}

// row accessors over per-pair register rows, any m in [-L+1, L-1]
// F_l^{-m} = (-1)^m conj(F_l^m)
template <int m, int L>
__device__ __forceinline__ float rr(const float (&re)[L]) {
    if constexpr (m >= 0) return re[m];
    else if constexpr ((-m) & 1) return -re[-m];
    else return re[-m];
}
template <int m, int L>
__device__ __forceinline__ float ri(const float (&im)[L]) {
    if constexpr (m >= 0) return im[m];
    else if constexpr ((-m) & 1) return im[-m];
    else return -im[-m];
}

// ---------------- per-group compute (one warp executes one group) ----------------
template <int G>
__device__ __forceinline__ void compute_group(
    const float* __restrict__ r,    // this lane's coeff re row [45]
    const float* __restrict__ q,    // this lane's coeff im row [45]
    float* __restrict__ ob)         // this lane's staged output row [NOUT]
{
    sfor<0, LMAX + 1>([&](auto L1c) {
        constexpr int l1 = decltype(L1c)::value;
        sfor<l1, LMAX + 1>([&](auto L2c) {
            constexpr int l2 = decltype(L2c)::value;
            if constexpr (pair_group(l1, l2) == G) {
                constexpr int lomin = l2 - l1;
                constexpr int lomax = imin(l1 + l2, LMAX);
                constexpr int nlo = lomax - lomin + 1;

                // load this pair's coefficient rows into registers
                float f1r[l1 + 1], f1i[l1 + 1];
                sfor<0, l1 + 1>([&](auto Mc) {
                    constexpr int m = decltype(Mc)::value;
                    f1r[m] = r[cpos(l1, m)]; f1i[m] = q[cpos(l1, m)];
                });
                float f2r[l2 + 1], f2i[l2 + 1];
                sfor<0, l2 + 1>([&](auto Mc) {
                    constexpr int m = decltype(Mc)::value;
                    f2r[m] = r[cpos(l2, m)]; f2i[m] = q[cpos(l2, m)];
                });

                float beta[nlo], pw[nlo];
                sfor<0, nlo>([&](auto Ic) {
                    constexpr int i = decltype(Ic)::value;
                    beta[i] = 0.f; pw[i] = 0.f;
                });

                sfor<-(l1 + l2), l1 + l2 + 1>([&](auto MMc) {
                    constexpr int M = decltype(MMc)::value;
                    constexpr int lstart = imax(lomin, iabs(M));
                    if constexpr (lstart <= lomax) {
                        constexpr int ng = lomax - lstart + 1;
                        float gre[ng], gim[ng];
                        sfor<0, ng>([&](auto Ic) {
                            constexpr int i = decltype(Ic)::value;
                            gre[i] = 0.f; gim[i] = 0.f;
                        });

                        constexpr int m1lo = imax(-l1, M - l2);
                        constexpr int m1hi = imin(l1, M + l2);
                        sfor<m1lo, m1hi + 1>([&](auto M1c) {
                            constexpr int m1 = decltype(M1c)::value;
                            constexpr int m2 = M - m1;
                            // l1==l2: fold (m1,m2)+(m2,m1), keep m1<=m2 only
                            if constexpr (!(l1 == l2 && m1 > m2)) {
                                float are = rr<m1>(f1r), aim = ri<m1>(f1i);
                                float bre = rr<m2>(f2r), bim = ri<m2>(f2i);
                                float p_re = are * bre - aim * bim;
                                float p_im = are * bim + aim * bre;
                                sfor<lstart, lomax + 1>([&](auto LOc) {
                                    constexpr int lo = decltype(LOc)::value;
                                    constexpr double c0 = cg(l1, m1, l2, m2, lo, M);
                                    constexpr double cc = (l1 == l2 && m1 < m2)
                                        ? c0 + cg(l1, m2, l2, m1, lo, M) : c0;
                                    if constexpr (cc != 0.0) {
                                        constexpr float cf = (float)cc;
                                        gre[lo - lstart] += cf * p_re;   // FFMA-imm
                                        gim[lo - lstart] += cf * p_im;   // FFMA-imm
                                    }
                                });
                            }
                        });

                        // contract with conj(F_lo^M) + CG-power norms; F_lo^|M| from SMEM
                        constexpr int am = M < 0 ? -M : M;
                        sfor<lstart, lomax + 1>([&](auto LOc) {
                            constexpr int lo = decltype(LOc)::value;
                            float g_re = gre[lo - lstart], g_im = gim[lo - lstart];
                            float v_re = r[cpos(lo, am)], v_im = q[cpos(lo, am)];
                            float f3re, f3im;
                            if constexpr (M >= 0)      { f3re =  v_re; f3im =  v_im; }
                            else if constexpr (am & 1) { f3re = -v_re; f3im =  v_im; }
                            else                       { f3re =  v_re; f3im = -v_im; }
                            beta[lo - lomin] += g_re * f3re + g_im * f3im;
                            if constexpr (power_index(l1, l2, lo) >= 0) {
                                pw[lo - lomin] += g_re * g_re + g_im * g_im;
                            }
                        });
                    }
                });

                // stage outputs for this (l1,l2) block into SMEM
                sfor<lomin, lomax + 1>([&](auto LOc) {
                    constexpr int lo = decltype(LOc)::value;
                    constexpr int fidx = full_index(l1, l2, lo);
                    ob[fidx] = beta[lo - lomin];
                    constexpr int pidx = power_index(l1, l2, lo);
                    if constexpr (pidx >= 0) {
                        ob[NFULL + pidx] = pw[lo - lomin];
                    }
                });
            }
        });
    });
}

// ---------------- kernel ----------------
// 128 threads = 4 warps; warp w computes pair-group w for 32 batch elements (lane = element).
__global__ void __launch_bounds__(TPB, 4) bispec_kernel(
    const float* __restrict__ cre, const float* __restrict__ cim,
    float* __restrict__ out, int batch)
{
    __shared__ float sre[EPB * NCMP];     // [elem][cpos], lane stride 45 -> conflict-free
    __shared__ float sim[EPB * NCMP];
    __shared__ float sout[EPB * NOUT];    // [elem][out], staged for coalesced writeback

    const int tid  = threadIdx.x;
    const int w    = tid >> 5;
    const int lane = tid & 31;
    const int blk_base = blockIdx.x * EPB;
    const int nvalid = imin(EPB, batch - blk_base);

    // ---- stage + compact coefficients into SMEM (coalesced global reads) ----
    for (int g = tid; g < EPB * NCOEF; g += TPB) {
        const int e = g / NCOEF;
        const int c = g - e * NCOEF;
        if (e < nvalid) {
            const int l = c / (LMAX + 1);
            const int m = c - l * (LMAX + 1);
            if (m <= l) {
                const size_t gidx = (size_t)(blk_base + e) * NCOEF + c;
                sre[e * NCMP + cpos(l, m)] = cre[gidx];
                sim[e * NCMP + cpos(l, m)] = cim[gidx];
            }
        }
    }
    __syncthreads();

    // ---- warp-specialized compute (branches are warp-uniform; no divergence) ----
    {
        const float* r = sre + lane * NCMP;
        const float* q = sim + lane * NCMP;
        float* ob = sout + lane * NOUT;
        if      (w == 0) compute_group<0>(r, q, ob);
        else if (w == 1) compute_group<1>(r, q, ob);
        else if (w == 2) compute_group<2>(r, q, ob);
        else             compute_group<3>(r, q, ob);
    }
    __syncthreads();

    // ---- coalesced writeback: sout is exactly [elem][out] flat ----
    const int total = nvalid * NOUT;
    const size_t obase = (size_t)blk_base * NOUT;
    for (int t = tid; t < total; t += TPB)
        out[obase + t] = sout[t];
}

} // namespace so3

extern "C" void kernel_launch(void* const* d_in, const int* in_sizes, int n_in,
                              void* d_out, int out_size) {
    const float* cre = (const float*)d_in[0];
    const float* cim = (const float*)d_in[1];
    float* out = (float*)d_out;
    const int batch = in_sizes[0] / so3::NCOEF;
    const int blocks = (batch + so3::EPB - 1) / so3::EPB;
    so3::bispec_kernel<<<blocks, so3::TPB>>>(cre, cim, out, batch);
}

// round 15
// speedup vs baseline: 1.1251x; 1.1251x over previous
#include <cuda_runtime.h>
#include <type_traits>
#include <cstddef>

namespace so3 {

constexpr int LMAX  = 8;
constexpr int NCOEF = (LMAX + 1) * (LMAX + 1);   // 81 per batch per array
constexpr int NCMP  = 45;                        // compact m>=0 coefficients
constexpr int TPB   = 128;
constexpr int EPB   = 32;                        // batch elements per block (one per lane)
constexpr int NGRP  = 4;                         // pair groups = warps per block

// ---------------- compile-time math ----------------
__host__ __device__ constexpr double fact(int n) { double r = 1.0; for (int i = 2; i <= n; ++i) r *= (double)i; return r; }
__host__ __device__ constexpr double csqrt(double x) {
    if (x <= 0.0) return 0.0;
    double g = x > 1.0 ? x : 1.0;
    for (int i = 0; i < 64; ++i) g = 0.5 * (g + x / g);
    return g;
}
__host__ __device__ constexpr int iabs(int x) { return x < 0 ? -x : x; }
__host__ __device__ constexpr int imin(int a, int b) { return a < b ? a : b; }
__host__ __device__ constexpr int imax(int a, int b) { return a > b ? a : b; }
__host__ __device__ constexpr int cpos(int l, int m) { return l * (l + 1) / 2 + m; }   // 0..44

// Clebsch-Gordan <j1 m1 j2 m2 | j3 m3>, Racah formula (matches reference)
__host__ __device__ constexpr double cg(int j1, int m1, int j2, int m2, int j3, int m3) {
    if (m1 + m2 != m3) return 0.0;
    if (j3 < iabs(j1 - j2) || j3 > j1 + j2) return 0.0;
    if (iabs(m1) > j1 || iabs(m2) > j2 || iabs(m3) > j3) return 0.0;
    double pre = csqrt((2.0 * j3 + 1.0) * fact(j1 + j2 - j3) * fact(j1 - j2 + j3) *
                       fact(-j1 + j2 + j3) / fact(j1 + j2 + j3 + 1));
    pre *= csqrt(fact(j1 + m1) * fact(j1 - m1) * fact(j2 + m2) * fact(j2 - m2) *
                 fact(j3 + m3) * fact(j3 - m3));
    int kmin = imax(0, imax(j2 - j3 - m1, j1 - j3 + m2));
    int kmax = imin(j1 + j2 - j3, imin(j1 - m1, j2 + m2));
    double s = 0.0;
    for (int k = kmin; k <= kmax; ++k) {
        double d = fact(k) * fact(j1 + j2 - j3 - k) * fact(j1 - m1 - k) *
                   fact(j2 + m2 - k) * fact(j3 - j2 + m1 + k) * fact(j3 - j1 - m2 + k);
        s += ((k & 1) ? -1.0 : 1.0) / d;
    }
    return pre * s;
}

// ---------------- output index maps (mirror reference builders) ----------------
__host__ __device__ constexpr int full_index(int a, int b, int c) {
    int idx = 0;
    for (int l1 = 0; l1 <= LMAX; ++l1)
        for (int l2 = l1; l2 <= LMAX; ++l2)
            for (int lv = l2 - l1; lv <= imin(l1 + l2, LMAX); ++lv) {
                if (l1 == a && l2 == b && lv == c) return idx;
                ++idx;
            }
    return -1;
}
__host__ __device__ constexpr int count_full() {
    int idx = 0;
    for (int l1 = 0; l1 <= LMAX; ++l1)
        for (int l2 = l1; l2 <= LMAX; ++l2)
            for (int lv = l2 - l1; lv <= imin(l1 + l2, LMAX); ++lv) ++idx;
    return idx;
}
constexpr int NFULL = count_full();
static_assert(NFULL == 215, "FULL map size mismatch");

__host__ __device__ constexpr int power_index_impl(int a, int b, int c) {
    int idx = 0;
    for (int l2 = 2; l2 <= LMAX; ++l2) {
        if (a == 1 && b == l2 && c == l2 - 1) return idx;
        ++idx;
        if (l2 >= 4 && (l2 - 1) + 1 <= imin(l2 + 1, LMAX)) {
            if (a == 1 && b == l2 && c == l2) return idx;
            ++idx;
        }
    }
    for (int l2 = 3; l2 <= LMAX; ++l2) {
        if (a == 2 && b == l2 && c == l2 - 2) return idx;
        ++idx;
        if ((l2 - 2) + 1 <= imin(l2 + 2, LMAX)) {
            if (a == 2 && b == l2 && c == l2 - 1) return idx;
            ++idx;
        }
    }
    if (LMAX >= 3) {
        if (a == 3 && b == 3 && c == 2) return idx;
        ++idx;
    }
    for (int l2 = 4; l2 <= LMAX; ++l2) {
        if (a == 3 && b == l2 && c == l2 - 3) return idx;
        ++idx;
        if ((l2 % 2 == 1) && l2 >= 5) {
            if ((l2 - 3) + 1 <= imin(l2 + 3, LMAX)) {
                if (a == 3 && b == l2 && c == l2 - 2) return idx;
                ++idx;
            }
            if ((l2 - 3) + 2 <= imin(l2 + 3, LMAX)) {
                if (a == 3 && b == l2 && c == l2 - 1) return idx;
                ++idx;
            }
        }
    }
    return 1000 + idx;
}
__host__ __device__ constexpr int power_index(int a, int b, int c) {
    return power_index_impl(a, b, c) >= 1000 ? -1 : power_index_impl(a, b, c);
}
constexpr int NPOWER = power_index_impl(-9, -9, -9) - 1000;
static_assert(NPOWER == 34, "POWER map size mismatch");
constexpr int NOUT = NFULL + NPOWER;   // 249

// ---------------- compile-time pair partition (greedy, largest-first) ----------------
constexpr int NPAIRS = (LMAX + 1) * (LMAX + 2) / 2;   // 45

__host__ __device__ constexpr int pair_index(int a, int b) {
    int idx = 0;
    for (int l1 = 0; l1 <= LMAX; ++l1)
        for (int l2 = l1; l2 <= LMAX; ++l2) { if (l1 == a && l2 == b) return idx; ++idx; }
    return -1;
}

// Analytic FFMA-issue cost proxy of one (l1,l2) pair — NO cg() calls (cheap constexpr).
__host__ __device__ constexpr long pair_cost(int l1, int l2) {
    long c = 0;
    const int lomin = l2 - l1, lomax = imin(l1 + l2, LMAX);
    for (int M = -(l1 + l2); M <= l1 + l2; ++M) {
        int lstart = imax(lomin, iabs(M));
        if (lstart > lomax) continue;
        int nlo = lomax - lstart + 1;
        for (int m1 = imax(-l1, M - l2); m1 <= imin(l1, M + l2); ++m1) {
            int m2 = M - m1;
            if (l1 == l2 && m1 > m2) continue;
            c += 6 + 2L * nlo;          // complex product + CG FMAs
        }
        for (int lo = lstart; lo <= lomax; ++lo) {
            c += 6;                     // beta dot + f3 fetch
            if (power_index(l1, l2, lo) >= 0) c += 4;
        }
    }
    return c;
}

struct PairAssign { int grp[NPAIRS]; };

__host__ __device__ constexpr PairAssign assign_pairs() {
    long cost[NPAIRS] = {};
    {
        int idx = 0;
        for (int l1 = 0; l1 <= LMAX; ++l1)
            for (int l2 = l1; l2 <= LMAX; ++l2) { cost[idx] = pair_cost(l1, l2); ++idx; }
    }
    bool used[NPAIRS] = {};
    long load[NGRP] = {};
    PairAssign pa = {};
    for (int it = 0; it < NPAIRS; ++it) {
        int best = -1;
        for (int p = 0; p < NPAIRS; ++p)
            if (!used[p] && (best < 0 || cost[p] > cost[best])) best = p;
        int g = 0;
        for (int k = 1; k < NGRP; ++k) if (load[k] < load[g]) g = k;
        pa.grp[best] = g; load[g] += cost[best]; used[best] = true;
    }
    return pa;
}
constexpr PairAssign PA = assign_pairs();
__host__ __device__ constexpr int pair_group(int l1, int l2) { return PA.grp[pair_index(l1, l2)]; }

// ---------------- static-for ----------------
template <int I, int N, class F>
__device__ __forceinline__ void sfor(F&& f) {
    if constexpr (I < N) {
        f(std::integral_constant<int, I>{});
        sfor<I + 1, N>(f);
    }
}

// row accessors over per-pair register rows, any m in [-L+1, L-1]
// F_l^{-m} = (-1)^m conj(F_l^m)
template <int m, int L>
__device__ __forceinline__ float rr(const float (&re)[L]) {
    if constexpr (m >= 0) return re[m];
    else if constexpr ((-m) & 1) return -re[-m];
    else return re[-m];
}
template <int m, int L>
__device__ __forceinline__ float ri(const float (&im)[L]) {
    if constexpr (m >= 0) return im[m];
    else if constexpr ((-m) & 1) return im[-m];
    else return -im[-m];
}

// ---------------- per-group compute (one warp executes one group) ----------------
template <int G>
__device__ __forceinline__ void compute_group(
    const float* __restrict__ r,    // this lane's coeff re row [45]
    const float* __restrict__ q,    // this lane's coeff im row [45]
    float* __restrict__ ob)         // this lane's staged output row [NOUT]
{
    sfor<0, LMAX + 1>([&](auto L1c) {
        constexpr int l1 = decltype(L1c)::value;
        sfor<l1, LMAX + 1>([&](auto L2c) {
            constexpr int l2 = decltype(L2c)::value;
            if constexpr (pair_group(l1, l2) == G) {
                constexpr int lomin = l2 - l1;
                constexpr int lomax = imin(l1 + l2, LMAX);
                constexpr int nlo = lomax - lomin + 1;

                // load this pair's coefficient rows into registers
                float f1r[l1 + 1], f1i[l1 + 1];
                sfor<0, l1 + 1>([&](auto Mc) {
                    constexpr int m = decltype(Mc)::value;
                    f1r[m] = r[cpos(l1, m)]; f1i[m] = q[cpos(l1, m)];
                });
                float f2r[l2 + 1], f2i[l2 + 1];
                sfor<0, l2 + 1>([&](auto Mc) {
                    constexpr int m = decltype(Mc)::value;
                    f2r[m] = r[cpos(l2, m)]; f2i[m] = q[cpos(l2, m)];
                });

                float beta[nlo], pw[nlo];
                sfor<0, nlo>([&](auto Ic) {
                    constexpr int i = decltype(Ic)::value;
                    beta[i] = 0.f; pw[i] = 0.f;
                });

                sfor<-(l1 + l2), l1 + l2 + 1>([&](auto MMc) {
                    constexpr int M = decltype(MMc)::value;
                    constexpr int lstart = imax(lomin, iabs(M));
                    if constexpr (lstart <= lomax) {
                        constexpr int ng = lomax - lstart + 1;
                        float gre[ng], gim[ng];
                        sfor<0, ng>([&](auto Ic) {
                            constexpr int i = decltype(Ic)::value;
                            gre[i] = 0.f; gim[i] = 0.f;
                        });

                        constexpr int m1lo = imax(-l1, M - l2);
                        constexpr int m1hi = imin(l1, M + l2);
                        sfor<m1lo, m1hi + 1>([&](auto M1c) {
                            constexpr int m1 = decltype(M1c)::value;
                            constexpr int m2 = M - m1;
                            // l1==l2: fold (m1,m2)+(m2,m1), keep m1<=m2 only
                            if constexpr (!(l1 == l2 && m1 > m2)) {
                                float are = rr<m1>(f1r), aim = ri<m1>(f1i);
                                float bre = rr<m2>(f2r), bim = ri<m2>(f2i);
                                float p_re = are * bre - aim * bim;
                                float p_im = are * bim + aim * bre;
                                sfor<lstart, lomax + 1>([&](auto LOc) {
                                    constexpr int lo = decltype(LOc)::value;
                                    constexpr double c0 = cg(l1, m1, l2, m2, lo, M);
                                    constexpr double cc = (l1 == l2 && m1 < m2)
                                        ? c0 + cg(l1, m2, l2, m1, lo, M) : c0;
                                    if constexpr (cc != 0.0) {
                                        constexpr float cf = (float)cc;
                                        gre[lo - lstart] += cf * p_re;   // FFMA-imm
                                        gim[lo - lstart] += cf * p_im;   // FFMA-imm
                                    }
                                });
                            }
                        });

                        // contract with conj(F_lo^M) + CG-power norms; F_lo^|M| from SMEM
                        constexpr int am = M < 0 ? -M : M;
                        sfor<lstart, lomax + 1>([&](auto LOc) {
                            constexpr int lo = decltype(LOc)::value;
                            float g_re = gre[lo - lstart], g_im = gim[lo - lstart];
                            float v_re = r[cpos(lo, am)], v_im = q[cpos(lo, am)];
                            float f3re, f3im;
                            if constexpr (M >= 0)      { f3re =  v_re; f3im =  v_im; }
                            else if constexpr (am & 1) { f3re = -v_re; f3im =  v_im; }
                            else                       { f3re =  v_re; f3im = -v_im; }
                            beta[lo - lomin] += g_re * f3re + g_im * f3im;
                            if constexpr (power_index(l1, l2, lo) >= 0) {
                                pw[lo - lomin] += g_re * g_re + g_im * g_im;
                            }
                        });
                    }
                });

                // stage outputs for this (l1,l2) block into SMEM
                sfor<lomin, lomax + 1>([&](auto LOc) {
                    constexpr int lo = decltype(LOc)::value;
                    constexpr int fidx = full_index(l1, l2, lo);
                    ob[fidx] = beta[lo - lomin];
                    constexpr int pidx = power_index(l1, l2, lo);
                    if constexpr (pidx >= 0) {
                        ob[NFULL + pidx] = pw[lo - lomin];
                    }
                });
            }
        });
    });
}

// ---------------- kernel ----------------
// 128 threads = 4 warps; warp w computes pair-group w for 32 batch elements (lane = element).
// NOTE: no min-blocks clause — let ptxas pick registers freely (R6/R9/R12 showed caps spill or serialize).
__global__ void __launch_bounds__(TPB) bispec_kernel(
    const float* __restrict__ cre, const float* __restrict__ cim,
    float* __restrict__ out, int batch)
{
    __shared__ float sre[EPB * NCMP];     // [elem][cpos], lane stride 45 -> conflict-free
    __shared__ float sim[EPB * NCMP];
    __shared__ float sout[EPB * NOUT];    // [elem][out], staged for coalesced writeback

    const int tid  = threadIdx.x;
    const int w    = tid >> 5;
    const int lane = tid & 31;
    const int blk_base = blockIdx.x * EPB;
    const int nvalid = imin(EPB, batch - blk_base);

    // ---- stage + compact coefficients into SMEM (coalesced global reads) ----
    for (int g = tid; g < EPB * NCOEF; g += TPB) {
        const int e = g / NCOEF;
        const int c = g - e * NCOEF;
        if (e < nvalid) {
            const int l = c / (LMAX + 1);
            const int m = c - l * (LMAX + 1);
            if (m <= l) {
                const size_t gidx = (size_t)(blk_base + e) * NCOEF + c;
                sre[e * NCMP + cpos(l, m)] = cre[gidx];
                sim[e * NCMP + cpos(l, m)] = cim[gidx];
            }
        }
    }
    __syncthreads();

    // ---- warp-specialized compute (branches are warp-uniform; no divergence) ----
    {
        const float* r = sre + lane * NCMP;
        const float* q = sim + lane * NCMP;
        float* ob = sout + lane * NOUT;
        if      (w == 0) compute_group<0>(r, q, ob);
        else if (w == 1) compute_group<1>(r, q, ob);
        else if (w == 2) compute_group<2>(r, q, ob);
        else             compute_group<3>(r, q, ob);
    }
    __syncthreads();

    // ---- coalesced writeback: sout is exactly [elem][out] flat ----
    const int total = nvalid * NOUT;
    const size_t obase = (size_t)blk_base * NOUT;
    for (int t = tid; t < total; t += TPB)
        out[obase + t] = sout[t];
}

} // namespace so3

extern "C" void kernel_launch(void* const* d_in, const int* in_sizes, int n_in,
                              void* d_out, int out_size) {
    const float* cre = (const float*)d_in[0];
    const float* cim = (const float*)d_in[1];
    float* out = (float*)d_out;
    const int batch = in_sizes[0] / so3::NCOEF;
    const int blocks = (batch + so3::EPB - 1) / so3::EPB;
    so3::bispec_kernel<<<blocks, so3::TPB>>>(cre, cim, out, batch);
}

// round 16
// speedup vs baseline: 1.4027x; 1.2468x over previous
#include <cuda_runtime.h>
#include <type_traits>
#include <cstddef>

namespace so3 {

constexpr int LMAX  = 8;
constexpr int NCOEF = (LMAX + 1) * (LMAX + 1);   // 81 per batch per array
constexpr int NCMP  = 45;                        // compact m>=0 coefficients
constexpr int TPB   = 128;                       // block = 128 threads = 128 batch elements

// ---------------- compile-time math ----------------
__host__ __device__ constexpr double fact(int n) { double r = 1.0; for (int i = 2; i <= n; ++i) r *= (double)i; return r; }
__host__ __device__ constexpr double csqrt(double x) {
    if (x <= 0.0) return 0.0;
    double g = x > 1.0 ? x : 1.0;
    for (int i = 0; i < 64; ++i) g = 0.5 * (g + x / g);
    return g;
}
__host__ __device__ constexpr int iabs(int x) { return x < 0 ? -x : x; }
__host__ __device__ constexpr int imin(int a, int b) { return a < b ? a : b; }
__host__ __device__ constexpr int imax(int a, int b) { return a > b ? a : b; }
__host__ __device__ constexpr int cpos(int l, int m) { return l * (l + 1) / 2 + m; }   // 0..44

// Clebsch-Gordan <j1 m1 j2 m2 | j3 m3>, Racah formula (matches reference)
__host__ __device__ constexpr double cg(int j1, int m1, int j2, int m2, int j3, int m3) {
    if (m1 + m2 != m3) return 0.0;
    if (j3 < iabs(j1 - j2) || j3 > j1 + j2) return 0.0;
    if (iabs(m1) > j1 || iabs(m2) > j2 || iabs(m3) > j3) return 0.0;
    double pre = csqrt((2.0 * j3 + 1.0) * fact(j1 + j2 - j3) * fact(j1 - j2 + j3) *
                       fact(-j1 + j2 + j3) / fact(j1 + j2 + j3 + 1));
    pre *= csqrt(fact(j1 + m1) * fact(j1 - m1) * fact(j2 + m2) * fact(j2 - m2) *
                 fact(j3 + m3) * fact(j3 - m3));
    int kmin = imax(0, imax(j2 - j3 - m1, j1 - j3 + m2));
    int kmax = imin(j1 + j2 - j3, imin(j1 - m1, j2 + m2));
    double s = 0.0;
    for (int k = kmin; k <= kmax; ++k) {
        double d = fact(k) * fact(j1 + j2 - j3 - k) * fact(j1 - m1 - k) *
                   fact(j2 + m2 - k) * fact(j3 - j2 + m1 + k) * fact(j3 - j1 - m2 + k);
        s += ((k & 1) ? -1.0 : 1.0) / d;
    }
    return pre * s;
}

// ---------------- output index maps (mirror reference builders) ----------------
__host__ __device__ constexpr int full_index(int a, int b, int c) {
    int idx = 0;
    for (int l1 = 0; l1 <= LMAX; ++l1)
        for (int l2 = l1; l2 <= LMAX; ++l2)
            for (int lv = l2 - l1; lv <= imin(l1 + l2, LMAX); ++lv) {
                if (l1 == a && l2 == b && lv == c) return idx;
                ++idx;
            }
    return -1;
}
__host__ __device__ constexpr int count_full() {
    int idx = 0;
    for (int l1 = 0; l1 <= LMAX; ++l1)
        for (int l2 = l1; l2 <= LMAX; ++l2)
            for (int lv = l2 - l1; lv <= imin(l1 + l2, LMAX); ++lv) ++idx;
    return idx;
}
constexpr int NFULL = count_full();
static_assert(NFULL == 215, "FULL map size mismatch");

__host__ __device__ constexpr int power_index_impl(int a, int b, int c) {
    int idx = 0;
    for (int l2 = 2; l2 <= LMAX; ++l2) {
        if (a == 1 && b == l2 && c == l2 - 1) return idx;
        ++idx;
        if (l2 >= 4 && (l2 - 1) + 1 <= imin(l2 + 1, LMAX)) {
            if (a == 1 && b == l2 && c == l2) return idx;
            ++idx;
        }
    }
    for (int l2 = 3; l2 <= LMAX; ++l2) {
        if (a == 2 && b == l2 && c == l2 - 2) return idx;
        ++idx;
        if ((l2 - 2) + 1 <= imin(l2 + 2, LMAX)) {
            if (a == 2 && b == l2 && c == l2 - 1) return idx;
            ++idx;
        }
    }
    if (LMAX >= 3) {
        if (a == 3 && b == 3 && c == 2) return idx;
        ++idx;
    }
    for (int l2 = 4; l2 <= LMAX; ++l2) {
        if (a == 3 && b == l2 && c == l2 - 3) return idx;
        ++idx;
        if ((l2 % 2 == 1) && l2 >= 5) {
            if ((l2 - 3) + 1 <= imin(l2 + 3, LMAX)) {
                if (a == 3 && b == l2 && c == l2 - 2) return idx;
                ++idx;
            }
            if ((l2 - 3) + 2 <= imin(l2 + 3, LMAX)) {
                if (a == 3 && b == l2 && c == l2 - 1) return idx;
                ++idx;
            }
        }
    }
    return 1000 + idx;
}
__host__ __device__ constexpr int power_index(int a, int b, int c) {
    return power_index_impl(a, b, c) >= 1000 ? -1 : power_index_impl(a, b, c);
}
constexpr int NPOWER = power_index_impl(-9, -9, -9) - 1000;
static_assert(NPOWER == 34, "POWER map size mismatch");
constexpr int NOUT = NFULL + NPOWER;   // 249

// ---------------- static-for ----------------
template <int I, int N, class F>
__device__ __forceinline__ void sfor(F&& f) {
    if constexpr (I < N) {
        f(std::integral_constant<int, I>{});
        sfor<I + 1, N>(f);
    }
}

// row accessors over padded [9] register rows, any m; F_l^{-m} = (-1)^m conj(F_l^m)
template <int m>
__device__ __forceinline__ float rr(const float (&re)[9]) {
    if constexpr (m >= 0) return re[m];
    else if constexpr ((-m) & 1) return -re[-m];
    else return re[-m];
}
template <int m>
__device__ __forceinline__ float ri(const float (&im)[9]) {
    if constexpr (m >= 0) return im[m];
    else if constexpr ((-m) & 1) return im[-m];
    else return -im[-m];
}

// ---------------- one (l1,l2) pair: G, beta, power, direct store ----------------
// f1/f2 rows in registers (padded to 9); f3 read from this lane's SMEM rows r/q.
// Body identical to the R13-verified compute (rel_err 8e-8).
template <int l1, int l2>
__device__ __forceinline__ void do_pair(
    const float (&f1r)[9], const float (&f1i)[9],
    const float (&f2r)[9], const float (&f2i)[9],
    const float* __restrict__ r, const float* __restrict__ q,
    float* __restrict__ ob)
{
    constexpr int lomin = l2 - l1;
    constexpr int lomax = imin(l1 + l2, LMAX);
    constexpr int nlo = lomax - lomin + 1;

    float beta[nlo], pw[nlo];
    sfor<0, nlo>([&](auto Ic) {
        constexpr int i = decltype(Ic)::value;
        beta[i] = 0.f; pw[i] = 0.f;
    });

    sfor<-(l1 + l2), l1 + l2 + 1>([&](auto MMc) {
        constexpr int M = decltype(MMc)::value;
        constexpr int lstart = imax(lomin, iabs(M));
        if constexpr (lstart <= lomax) {
            constexpr int ng = lomax - lstart + 1;
            float gre[ng], gim[ng];
            sfor<0, ng>([&](auto Ic) {
                constexpr int i = decltype(Ic)::value;
                gre[i] = 0.f; gim[i] = 0.f;
            });

            constexpr int m1lo = imax(-l1, M - l2);
            constexpr int m1hi = imin(l1, M + l2);
            sfor<m1lo, m1hi + 1>([&](auto M1c) {
                constexpr int m1 = decltype(M1c)::value;
                constexpr int m2 = M - m1;
                // l1==l2: fold (m1,m2)+(m2,m1), keep m1<=m2 only
                if constexpr (!(l1 == l2 && m1 > m2)) {
                    float are = rr<m1>(f1r), aim = ri<m1>(f1i);
                    float bre = rr<m2>(f2r), bim = ri<m2>(f2i);
                    float p_re = are * bre - aim * bim;
                    float p_im = are * bim + aim * bre;
                    sfor<lstart, lomax + 1>([&](auto LOc) {
                        constexpr int lo = decltype(LOc)::value;
                        constexpr double c0 = cg(l1, m1, l2, m2, lo, M);
                        constexpr double cc = (l1 == l2 && m1 < m2)
                            ? c0 + cg(l1, m2, l2, m1, lo, M) : c0;
                        if constexpr (cc != 0.0) {
                            constexpr float cf = (float)cc;
                            gre[lo - lstart] += cf * p_re;   // FFMA-imm
                            gim[lo - lstart] += cf * p_im;   // FFMA-imm
                        }
                    });
                }
            });

            // contract with conj(F_lo^M) + CG-power norms; F_lo^|M| from SMEM
            constexpr int am = M < 0 ? -M : M;
            sfor<lstart, lomax + 1>([&](auto LOc) {
                constexpr int lo = decltype(LOc)::value;
                float g_re = gre[lo - lstart], g_im = gim[lo - lstart];
                float v_re = r[cpos(lo, am)], v_im = q[cpos(lo, am)];
                float f3re, f3im;
                if constexpr (M >= 0)      { f3re =  v_re; f3im =  v_im; }
                else if constexpr (am & 1) { f3re = -v_re; f3im =  v_im; }
                else                       { f3re =  v_re; f3im = -v_im; }
                beta[lo - lomin] += g_re * f3re + g_im * f3im;
                if constexpr (power_index(l1, l2, lo) >= 0) {
                    pw[lo - lomin] += g_re * g_re + g_im * g_im;
                }
            });
        }
    });

    // direct global store for this (l1,l2) block
    sfor<lomin, lomax + 1>([&](auto LOc) {
        constexpr int lo = decltype(LOc)::value;
        constexpr int fidx = full_index(l1, l2, lo);
        ob[fidx] = beta[lo - lomin];
        constexpr int pidx = power_index(l1, l2, lo);
        if constexpr (pidx >= 0) {
            ob[NFULL + pidx] = pw[lo - lomin];
        }
    });
}

// load row l (m=0..l) from SMEM into padded register row
template <int l>
__device__ __forceinline__ void load_row(
    const float* __restrict__ r, const float* __restrict__ q,
    float (&fr)[9], float (&fi)[9])
{
    sfor<0, l + 1>([&](auto Mc) {
        constexpr int m = decltype(Mc)::value;
        fr[m] = r[cpos(l, m)]; fi[m] = q[cpos(l, m)];
    });
}

// ---------------- phases (selected by blockIdx.y; 3-way l2-range split) ----------------
// Phase 0: pairs with l2 <= 5            (f1+f2 rows 0..5 resident: 42 regs)
// Phase 1: pairs with l2 in {6,7}        (f2 rows 6,7 resident: 30 regs; f1 per-l1)
// Phase 2: pairs with l2 == 8            (f2 row 8 resident: 18 regs; f1 per-l1)

__device__ __forceinline__ void phase0(const float* r, const float* q, float* ob) {
    float Fr[6][9], Fi[6][9];
    sfor<0, 6>([&](auto Lc) {
        constexpr int l = decltype(Lc)::value;
        load_row<l>(r, q, Fr[l], Fi[l]);
    });
    sfor<0, 6>([&](auto L1c) {
        constexpr int l1 = decltype(L1c)::value;
        sfor<l1, 6>([&](auto L2c) {
            constexpr int l2 = decltype(L2c)::value;
            do_pair<l1, l2>(Fr[l1], Fi[l1], Fr[l2], Fi[l2], r, q, ob);
        });
    });
}

__device__ __forceinline__ void phase1(const float* r, const float* q, float* ob) {
    float F6r[9], F6i[9], F7r[9], F7i[9];
    load_row<6>(r, q, F6r, F6i);
    load_row<7>(r, q, F7r, F7i);
    sfor<0, 8>([&](auto L1c) {
        constexpr int l1 = decltype(L1c)::value;
        float Ar[9], Ai[9];
        load_row<l1>(r, q, Ar, Ai);
        if constexpr (l1 <= 6) do_pair<l1, 6>(Ar, Ai, F6r, F6i, r, q, ob);
        do_pair<l1, 7>(Ar, Ai, F7r, F7i, r, q, ob);
    });
}

__device__ __forceinline__ void phase2(const float* r, const float* q, float* ob) {
    float F8r[9], F8i[9];
    load_row<8>(r, q, F8r, F8i);
    sfor<0, 9>([&](auto L1c) {
        constexpr int l1 = decltype(L1c)::value;
        float Ar[9], Ai[9];
        load_row<l1>(r, q, Ar, Ai);
        do_pair<l1, 8>(Ar, Ai, F8r, F8i, r, q, ob);
    });
}

// ---------------- kernel ----------------
// grid = (ceil(batch/128), 3). Block (x,y): elements [x*128, x*128+128), phase y.
// No reg cap — natural live set is small per phase; spills must be zero.
__global__ void __launch_bounds__(TPB) bispec_kernel(
    const float* __restrict__ cre, const float* __restrict__ cim,
    float* __restrict__ out, int batch)
{
    __shared__ float sre[TPB * NCMP];   // 23040 B
    __shared__ float sim[TPB * NCMP];   // 23040 B  (total 46 KB < 48 KB static limit)

    const int tid = threadIdx.x;
    const int blk_base = blockIdx.x * TPB;
    const int b = blk_base + tid;
    const int nvalid = imin(TPB, batch - blk_base);

    // ---- stage + compact coefficients into SMEM (coalesced global reads) ----
    for (int g = tid; g < TPB * NCOEF; g += TPB) {
        const int e = g / NCOEF;
        const int c = g - e * NCOEF;
        if (e < nvalid) {
            const int l = c / (LMAX + 1);
            const int m = c - l * (LMAX + 1);
            if (m <= l) {
                const size_t gidx = (size_t)(blk_base + e) * NCOEF + c;
                sre[e * NCMP + cpos(l, m)] = cre[gidx];
                sim[e * NCMP + cpos(l, m)] = cim[gidx];
            }
        }
    }
    __syncthreads();

    if (b >= batch) return;

    const float* r = sre + tid * NCMP;   // stride 45 words: gcd(45,32)=1 -> conflict-free
    const float* q = sim + tid * NCMP;
    float* ob = out + (size_t)b * NOUT;

    if      (blockIdx.y == 0) phase0(r, q, ob);
    else if (blockIdx.y == 1) phase1(r, q, ob);
    else                      phase2(r, q, ob);
}

} // namespace so3

extern "C" void kernel_launch(void* const* d_in, const int* in_sizes, int n_in,
                              void* d_out, int out_size) {
    const float* cre = (const float*)d_in[0];
    const float* cim = (const float*)d_in[1];
    float* out = (float*)d_out;
    const int batch = in_sizes[0] / so3::NCOEF;
    dim3 grid((batch + so3::TPB - 1) / so3::TPB, 3);
    so3::bispec_kernel<<<grid, so3::TPB>>>(cre, cim, out, batch);
}